// round 13
// baseline (speedup 1.0000x reference)
#include <cuda_runtime.h>
#include <cuda_bf16.h>
#include <cstdint>

// Problem dims
#define BB 2
#define SS 2048
#define HH 1024
#define NH 16
#define DD 64
#define MM (BB * SS)       // 4096 rows
#define K3H (3 * HH)       // 3072

// GEMM tiling: 128x128 CTA, 8 warps, 64x32 warp tile, 3-stage cp.async, KC=32
#define MT 128
#define NT 128
#define KC 32
#define NCHUNK (HH / KC)   // 32
#define NSTAGE 3
#define TILE_F (MT * KC)                   // 4096 floats per tile-stage
#define SMEM_DYN (2 * NSTAGE * TILE_F * 4) // 98304 B

// Scratch (device globals; no allocation allowed)
__device__ float g_x [MM * HH];            // tf32-rounded hidden_states
__device__ float g_wi[K3H * HH];           // tf32-rounded w_in
__device__ float g_wo[HH * HH];            // tf32-rounded w_out
__device__ float g_q[BB * NH * SS * DD];   // [b][n][s][d], scaled, tf32-rounded
__device__ float g_k[BB * NH * SS * DD];   // [b][n][s][d], tf32-rounded
__device__ float g_v[BB * NH * DD * SS];   // [b][n][d][s], tf32-rounded
__device__ float g_o[MM * HH];             // [b*s][h], tf32-rounded

__device__ __forceinline__ uint32_t f2tf32(float x) {
    uint32_t r;
    asm("cvt.rna.tf32.f32 %0, %1;" : "=r"(r) : "f"(x));
    return r;
}
__device__ __forceinline__ float tf32f(float x) { return __uint_as_float(f2tf32(x)); }

__device__ __forceinline__ void mma_tf32(float* d, const uint32_t* a, const uint32_t* b) {
    asm volatile(
        "mma.sync.aligned.m16n8k8.row.col.f32.tf32.tf32.f32 "
        "{%0,%1,%2,%3}, {%4,%5,%6,%7}, {%8,%9}, {%0,%1,%2,%3};"
        : "+f"(d[0]), "+f"(d[1]), "+f"(d[2]), "+f"(d[3])
        : "r"(a[0]), "r"(a[1]), "r"(a[2]), "r"(a[3]), "r"(b[0]), "r"(b[1]));
}

__device__ __forceinline__ void ldsm4(uint32_t* r, const void* p) {
    uint32_t a = (uint32_t)__cvta_generic_to_shared(p);
    asm volatile("ldmatrix.sync.aligned.m8n8.x4.shared.b16 {%0,%1,%2,%3}, [%4];"
                 : "=r"(r[0]), "=r"(r[1]), "=r"(r[2]), "=r"(r[3]) : "r"(a));
}

// .cg: fill SMEM via L2, bypass L1
__device__ __forceinline__ void cp_async16(void* smem_dst, const void* gsrc) {
    uint32_t a = (uint32_t)__cvta_generic_to_shared(smem_dst);
    asm volatile("cp.async.cg.shared.global [%0], [%1], 16;" :: "r"(a), "l"(gsrc));
}
#define CP_COMMIT() asm volatile("cp.async.commit_group;" ::: "memory")
#define CP_WAIT(n)  asm volatile("cp.async.wait_group %0;" :: "n"(n) : "memory")

// ---------------------------------------------------------------------------
// Fused pre-round pass
// ---------------------------------------------------------------------------
#define NX4  (MM * HH / 4)
#define NWI4 (K3H * HH / 4)
#define NWO4 (HH * HH / 4)
__global__ void round_all(const float4* __restrict__ hs,
                          const float4* __restrict__ wi,
                          const float4* __restrict__ wo)
{
    const int i = blockIdx.x * blockDim.x + threadIdx.x;
    const float4* src;
    float* dst;
    int off;
    if (i < NX4)              { src = hs; dst = g_x;  off = i; }
    else if (i < NX4 + NWI4)  { src = wi; dst = g_wi; off = i - NX4; }
    else                      { src = wo; dst = g_wo; off = i - NX4 - NWI4; }
    float4 v = src[off];
    float4 w = make_float4(tf32f(v.x), tf32f(v.y), tf32f(v.z), tf32f(v.w));
    *(float4*)(dst + (long)off * 4) = w;
}

// ---------------------------------------------------------------------------
// tf32 mma.sync GEMM: KC=32 chunks, 3-stage cp.async(.cg), full 8-unit XOR
// swizzle (q' = q ^ (row&7)), depth-1 fragment pipeline over 4 k8-steps.
// Dynamic SMEM (96KB, opt-in per call).
// ---------------------------------------------------------------------------
template <int MODE>
__global__ void __launch_bounds__(256, 2)
gemm_mma(const float* __restrict__ bias, float* __restrict__ Y)
{
    extern __shared__ float sm[];
    // A stages: sm + s*TILE_F ; B stages: sm + (NSTAGE + s)*TILE_F

    const float* Aptr = (MODE == 1) ? (const float*)g_o : (const float*)g_x;
    const float* Bptr = (MODE == 1) ? (const float*)g_wo : (const float*)g_wi;

    const int t    = threadIdx.x;
    const int wid  = t >> 5;
    const int lane = t & 31;
    const int g    = lane >> 2;
    const int c    = lane & 3;
    const int wm   = (wid >> 2) * 64;
    const int wn   = (wid & 3) * 32;
    const int m0   = blockIdx.y * MT;
    const int n0   = blockIdx.x * NT;

    const int a_row = ((lane >> 3) & 1) * 8 + (lane & 7);
    const int a_q   = lane >> 4;                // 0/1
    const int a_swb = a_row & 7;
    const int b_row = ((lane >> 4) & 1) * 8 + (lane & 7);
    const int b_q   = (lane >> 3) & 1;
    const int b_swb = b_row & 7;

    // cp.async mapping: row = t>>1 (0..127), 4 consecutive 16B units q0=(t&1)*4
    const int lrow = t >> 1;
    const int q0w  = (t & 1) * 4;
    const int rsw  = lrow & 7;
    const float* Ag = Aptr + (long)(m0 + lrow) * HH + q0w * 4;
    const float* Bg = Bptr + (long)(n0 + lrow) * HH + q0w * 4;
    float* AsRow = sm + lrow * KC;                      // + stage*TILE_F
    float* BsRow = sm + NSTAGE * TILE_F + lrow * KC;

    float acc[4][4][4];
#pragma unroll
    for (int mi = 0; mi < 4; mi++)
#pragma unroll
        for (int ni = 0; ni < 4; ni++)
#pragma unroll
            for (int k = 0; k < 4; k++) acc[mi][ni][k] = 0.f;

#pragma unroll
    for (int s = 0; s < 2; s++) {
        const float* Ags = Ag + s * KC;
        const float* Bgs = Bg + s * KC;
#pragma unroll
        for (int j = 0; j < 4; j++) {
            const int sq = ((q0w + j) ^ rsw) * 4;
            cp_async16(AsRow + s * TILE_F + sq, Ags + j * 4);
            cp_async16(BsRow + s * TILE_F + sq, Bgs + j * 4);
        }
        CP_COMMIT();
    }

    int st = 0, sf = 2;
#pragma unroll 1
    for (int kt = 0; kt < NCHUNK; kt++) {
        CP_WAIT(1);
        __syncthreads();

        if (kt + 2 < NCHUNK) {
            const float* Agn = Ag + (kt + 2) * KC;
            const float* Bgn = Bg + (kt + 2) * KC;
#pragma unroll
            for (int j = 0; j < 4; j++) {
                const int sq = ((q0w + j) ^ rsw) * 4;
                cp_async16(AsRow + sf * TILE_F + sq, Agn + j * 4);
                cp_async16(BsRow + sf * TILE_F + sq, Bgn + j * 4);
            }
            CP_COMMIT();
        }

        const float* As = sm + st * TILE_F;
        const float* Bs = sm + (NSTAGE + st) * TILE_F;

        // depth-1 fragment pipeline over 4 k8-steps
        uint32_t af[2][4][4], bfp[2][2][4];
        {
            const int qa = (0 + a_q) ^ a_swb;
            const int qb = (0 + b_q) ^ b_swb;
#pragma unroll
            for (int mi = 0; mi < 4; mi++)
                ldsm4(af[0][mi], As + (wm + mi * 16 + a_row) * KC + qa * 4);
            ldsm4(bfp[0][0], Bs + (wn + b_row) * KC + qb * 4);
            ldsm4(bfp[0][1], Bs + (wn + 16 + b_row) * KC + qb * 4);
        }
#pragma unroll
        for (int ks = 0; ks < 4; ks++) {
            const int cur = ks & 1, nxt = cur ^ 1;
            if (ks < 3) {
                const int qa = (2 * (ks + 1) + a_q) ^ a_swb;
                const int qb = (2 * (ks + 1) + b_q) ^ b_swb;
#pragma unroll
                for (int mi = 0; mi < 4; mi++)
                    ldsm4(af[nxt][mi], As + (wm + mi * 16 + a_row) * KC + qa * 4);
                ldsm4(bfp[nxt][0], Bs + (wn + b_row) * KC + qb * 4);
                ldsm4(bfp[nxt][1], Bs + (wn + 16 + b_row) * KC + qb * 4);
            }
#pragma unroll
            for (int mi = 0; mi < 4; mi++) {
                mma_tf32(acc[mi][0], af[cur][mi], &bfp[cur][0][0]);
                mma_tf32(acc[mi][1], af[cur][mi], &bfp[cur][0][2]);
                mma_tf32(acc[mi][2], af[cur][mi], &bfp[cur][1][0]);
                mma_tf32(acc[mi][3], af[cur][mi], &bfp[cur][1][2]);
            }
        }

        st = (st == NSTAGE - 1) ? 0 : st + 1;
        sf = (sf == NSTAGE - 1) ? 0 : sf + 1;
    }

    // Epilogue
#pragma unroll
    for (int ni = 0; ni < 4; ni++) {
        const int col = n0 + wn + ni * 8 + 2 * c;
        const float b0 = bias[col];
        const float b1 = bias[col + 1];
#pragma unroll
        for (int mi = 0; mi < 4; mi++) {
            const int r1 = m0 + wm + mi * 16 + g;
            const int r2 = r1 + 8;
            if (MODE == 0) {
                const int which = col >> 10;
                const int hn    = (col & 1023) >> 6;
                const int d     = col & 63;
                const float scale = (which == 0) ? 0.125f : 1.0f;
                const int bb1 = r1 >> 11, s1 = r1 & 2047;
                const int bb2 = r2 >> 11, s2 = r2 & 2047;
                float2 v1 = make_float2(tf32f((acc[mi][ni][0] + b0) * scale),
                                        tf32f((acc[mi][ni][1] + b1) * scale));
                float2 v2 = make_float2(tf32f((acc[mi][ni][2] + b0) * scale),
                                        tf32f((acc[mi][ni][3] + b1) * scale));
                if (which == 2) {
                    float* p1 = g_v + ((long)(bb1 * NH + hn) * DD + d) * SS + s1;
                    float* p2 = g_v + ((long)(bb2 * NH + hn) * DD + d) * SS + s2;
                    p1[0] = v1.x; p1[SS] = v1.y;
                    p2[0] = v2.x; p2[SS] = v2.y;
                } else {
                    float* dst0 = (which == 0) ? g_q : g_k;
                    *(float2*)(dst0 + (((long)(bb1 * NH + hn) * SS) + s1) * DD + d) = v1;
                    *(float2*)(dst0 + (((long)(bb2 * NH + hn) * SS) + s2) * DD + d) = v2;
                }
            } else {
                float2 v1 = make_float2(acc[mi][ni][0] + b0, acc[mi][ni][1] + b1);
                float2 v2 = make_float2(acc[mi][ni][2] + b0, acc[mi][ni][3] + b1);
                *(float2*)(Y + (long)r1 * HH + col) = v1;
                *(float2*)(Y + (long)r2 * HH + col) = v2;
            }
        }
    }
}

// ---------------------------------------------------------------------------
// Kernel 2: causal flash attention (unchanged from R12 / known-good)
// ---------------------------------------------------------------------------
__global__ void __launch_bounds__(256, 2) flash_attn_mma()
{
    __shared__ float Ks[32][68];    // [kv][d]
    __shared__ float Vs[64][36];    // [d][kv]
    __shared__ float Ps[128][36];   // [qrow][kv]

    const int t    = threadIdx.x;
    const int wid  = t >> 5;
    const int lane = t & 31;
    const int g    = lane >> 2;
    const int c    = lane & 3;
    const int bn   = blockIdx.y;
    const int q0   = (gridDim.x - 1 - blockIdx.x) * 128;   // heavy tiles first
    const int wr   = wid * 16;

    const int a_row = ((lane >> 3) & 1) * 8 + (lane & 7);
    const int a_kof = (lane >> 4) * 4;
    const int b_row = ((lane >> 4) & 1) * 8 + (lane & 7);
    const int b_kof = ((lane >> 3) & 1) * 4;

    const float* Qp = g_q + (long)bn * SS * DD;
    const float* Kp = g_k + (long)bn * SS * DD;
    const float* Vp = g_v + (long)bn * DD * SS;

    const int k_row0 = t >> 4;
    const int k_c4   = (t & 15) * 4;
    const int v_row0 = t >> 3;
    const int v_s4   = (t & 7) * 4;

    uint32_t Qf[8][4];
    {
        const float* qr0 = Qp + (long)(q0 + wr + g) * DD;
        const float* qr1 = qr0 + 8 * DD;
#pragma unroll
        for (int kc = 0; kc < 8; kc++) {
            Qf[kc][0] = __float_as_uint(qr0[kc * 8 + c]);
            Qf[kc][1] = __float_as_uint(qr1[kc * 8 + c]);
            Qf[kc][2] = __float_as_uint(qr0[kc * 8 + c + 4]);
            Qf[kc][3] = __float_as_uint(qr1[kc * 8 + c + 4]);
        }
    }

    float O[8][4];
#pragma unroll
    for (int dn = 0; dn < 8; dn++)
#pragma unroll
        for (int k = 0; k < 4; k++) O[dn][k] = 0.f;
    float m0v = -1e30f, m1v = -1e30f, l0 = 0.f, l1 = 0.f;

    const int r0g = q0 + wr + g;
    const int r1g = r0g + 8;
    const int nkt = (q0 + 128) >> 5;

    float4 ka[2], va[2];
#pragma unroll
    for (int p = 0; p < 2; p++) {
        ka[p] = *(const float4*)(Kp + (long)(k_row0 + p * 16) * DD + k_c4);
        va[p] = *(const float4*)(Vp + (long)(v_row0 + p * 32) * SS + v_s4);
    }

    for (int kt = 0; kt < nkt; kt++) {
        const int k0 = kt * 32;
        __syncthreads();
#pragma unroll
        for (int p = 0; p < 2; p++) {
            *(float4*)&Ks[k_row0 + p * 16][k_c4] = ka[p];
            *(float4*)&Vs[v_row0 + p * 32][v_s4] = va[p];
        }
        __syncthreads();

        if (kt + 1 < nkt) {
            const int kn = k0 + 32;
#pragma unroll
            for (int p = 0; p < 2; p++) {
                ka[p] = *(const float4*)(Kp + (long)(kn + k_row0 + p * 16) * DD + k_c4);
                va[p] = *(const float4*)(Vp + (long)(v_row0 + p * 32) * SS + kn + v_s4);
            }
        }

        float S[4][4];
#pragma unroll
        for (int ni = 0; ni < 4; ni++)
#pragma unroll
            for (int k = 0; k < 4; k++) S[ni][k] = 0.f;

        uint32_t btA[4], btB[4];
        ldsm4(btA, &Ks[b_row][b_kof]);
        ldsm4(btB, &Ks[16 + b_row][b_kof]);
#pragma unroll
        for (int kc = 0; kc < 8; kc++) {
            uint32_t nA[4], nB[4];
            if (kc < 7) {
                ldsm4(nA, &Ks[b_row][(kc + 1) * 8 + b_kof]);
                ldsm4(nB, &Ks[16 + b_row][(kc + 1) * 8 + b_kof]);
            }
            mma_tf32(S[0], Qf[kc], &btA[0]);
            mma_tf32(S[1], Qf[kc], &btA[2]);
            mma_tf32(S[2], Qf[kc], &btB[0]);
            mma_tf32(S[3], Qf[kc], &btB[2]);
            if (kc < 7) {
#pragma unroll
                for (int z = 0; z < 4; z++) { btA[z] = nA[z]; btB[z] = nB[z]; }
            }
        }

        float mx0 = m0v, mx1 = m1v;
#pragma unroll
        for (int ni = 0; ni < 4; ni++) {
            const int col0 = k0 + ni * 8 + 2 * c;
            const int col1 = col0 + 1;
            if (col0 > r0g) S[ni][0] = -1e30f;
            if (col1 > r0g) S[ni][1] = -1e30f;
            if (col0 > r1g) S[ni][2] = -1e30f;
            if (col1 > r1g) S[ni][3] = -1e30f;
            mx0 = fmaxf(mx0, fmaxf(S[ni][0], S[ni][1]));
            mx1 = fmaxf(mx1, fmaxf(S[ni][2], S[ni][3]));
        }
        mx0 = fmaxf(mx0, __shfl_xor_sync(0xffffffffu, mx0, 1));
        mx0 = fmaxf(mx0, __shfl_xor_sync(0xffffffffu, mx0, 2));
        mx1 = fmaxf(mx1, __shfl_xor_sync(0xffffffffu, mx1, 1));
        mx1 = fmaxf(mx1, __shfl_xor_sync(0xffffffffu, mx1, 2));

        const float a0 = __expf(m0v - mx0);
        const float a1 = __expf(m1v - mx1);
        m0v = mx0; m1v = mx1;

        float rs0 = 0.f, rs1 = 0.f;
#pragma unroll
        for (int ni = 0; ni < 4; ni++) {
            float p00 = __expf(S[ni][0] - mx0);
            float p01 = __expf(S[ni][1] - mx0);
            float p10 = __expf(S[ni][2] - mx1);
            float p11 = __expf(S[ni][3] - mx1);
            rs0 += p00 + p01; rs1 += p10 + p11;
            *(float2*)&Ps[wr + g][ni * 8 + 2 * c]     = make_float2(tf32f(p00), tf32f(p01));
            *(float2*)&Ps[wr + g + 8][ni * 8 + 2 * c] = make_float2(tf32f(p10), tf32f(p11));
        }
        rs0 += __shfl_xor_sync(0xffffffffu, rs0, 1);
        rs0 += __shfl_xor_sync(0xffffffffu, rs0, 2);
        rs1 += __shfl_xor_sync(0xffffffffu, rs1, 1);
        rs1 += __shfl_xor_sync(0xffffffffu, rs1, 2);
        l0 = l0 * a0 + rs0;
        l1 = l1 * a1 + rs1;

#pragma unroll
        for (int dn = 0; dn < 8; dn++) {
            O[dn][0] *= a0; O[dn][1] *= a0;
            O[dn][2] *= a1; O[dn][3] *= a1;
        }
        __syncwarp();

        uint32_t Af[4];
        ldsm4(Af, &Ps[wr + a_row][a_kof]);
#pragma unroll
        for (int j = 0; j < 4; j++) {
            uint32_t Afn[4];
            if (j < 3) ldsm4(Afn, &Ps[wr + a_row][(j + 1) * 8 + a_kof]);
#pragma unroll
            for (int dnp = 0; dnp < 4; dnp++) {
                uint32_t bt[4];
                ldsm4(bt, &Vs[dnp * 16 + b_row][j * 8 + b_kof]);
                mma_tf32(O[dnp * 2 + 0], Af, &bt[0]);
                mma_tf32(O[dnp * 2 + 1], Af, &bt[2]);
            }
            if (j < 3) {
#pragma unroll
                for (int z = 0; z < 4; z++) Af[z] = Afn[z];
            }
        }
    }

    const float inv0 = 1.0f / l0;
    const float inv1 = 1.0f / l1;
    const int b  = bn >> 4;
    const int hn = bn & 15;
    float* orow0 = g_o + (long)(b * SS + r0g) * HH + hn * DD;
    float* orow1 = orow0 + 8 * HH;
#pragma unroll
    for (int dn = 0; dn < 8; dn++) {
        *(float2*)(orow0 + dn * 8 + 2 * c) =
            make_float2(tf32f(O[dn][0] * inv0), tf32f(O[dn][1] * inv0));
        *(float2*)(orow1 + dn * 8 + 2 * c) =
            make_float2(tf32f(O[dn][2] * inv1), tf32f(O[dn][3] * inv1));
    }
}

// ---------------------------------------------------------------------------
extern "C" void kernel_launch(void* const* d_in, const int* in_sizes, int n_in,
                              void* d_out, int out_size)
{
    const float* hs    = (const float*)d_in[0];  // [B,S,H]
    const float* w_in  = (const float*)d_in[1];  // [3H,H]
    const float* b_in  = (const float*)d_in[2];  // [3H]
    const float* w_out = (const float*)d_in[3];  // [H,H]
    const float* b_out = (const float*)d_in[4];  // [H]
    float* out = (float*)d_out;                  // [B,S,H]

    (void)in_sizes; (void)n_in; (void)out_size;

    // Per-call opt-in for 96KB dynamic SMEM (idempotent, no static guard,
    // not a stream op -> graph-capture safe).
    cudaFuncSetAttribute(gemm_mma<0>, cudaFuncAttributeMaxDynamicSharedMemorySize, SMEM_DYN);
    cudaFuncSetAttribute(gemm_mma<1>, cudaFuncAttributeMaxDynamicSharedMemorySize, SMEM_DYN);

    round_all<<<(NX4 + NWI4 + NWO4) / 256, 256>>>(
        (const float4*)hs, (const float4*)w_in, (const float4*)w_out);

    gemm_mma<0><<<dim3(K3H / NT, MM / MT), 256, SMEM_DYN>>>(b_in, nullptr);
    flash_attn_mma<<<dim3(SS / 128, BB * NH), 256>>>();
    gemm_mma<1><<<dim3(HH / NT, MM / MT), 256, SMEM_DYN>>>(b_out, out);
}

// round 14
// speedup vs baseline: 1.7215x; 1.7215x over previous
#include <cuda_runtime.h>
#include <cuda_fp16.h>
#include <cstdint>

// Problem dims
#define BB 2
#define SS 2048
#define HH 1024
#define NH 16
#define DD 64
#define MM (BB * SS)       // 4096 rows
#define K3H (3 * HH)       // 3072

// GEMM tiling: 128x128 CTA, 8 warps, 64x32 warp tile, fp16 m16n8k16
#define MT 128
#define NT 128
#define KCH 64             // halves per k-chunk (128B rows)
#define NCHUNK (HH / KCH)  // 16
#define NSTAGE 3
#define TILE_H (MT * KCH)                   // 8192 halves = 16KB per tile
#define SMEM_DYN (2 * NSTAGE * TILE_H * 2)  // 98304 B

// Scratch (device globals; no allocation allowed) -- all fp16
__device__ __half g_x [MM * HH];            // fp16 hidden_states
__device__ __half g_wi[K3H * HH];           // fp16 w_in
__device__ __half g_wo[HH * HH];            // fp16 w_out
__device__ __half g_q[BB * NH * SS * DD];   // [b][n][s][d], scaled
__device__ __half g_k[BB * NH * SS * DD];   // [b][n][s][d]
__device__ __half g_v[BB * NH * DD * SS];   // [b][n][d][s]
__device__ __half g_o[MM * HH];             // [b*s][h]

__device__ __forceinline__ void mma_f16(float* d, const uint32_t* a, const uint32_t* b) {
    asm volatile(
        "mma.sync.aligned.m16n8k16.row.col.f32.f16.f16.f32 "
        "{%0,%1,%2,%3}, {%4,%5,%6,%7}, {%8,%9}, {%0,%1,%2,%3};"
        : "+f"(d[0]), "+f"(d[1]), "+f"(d[2]), "+f"(d[3])
        : "r"(a[0]), "r"(a[1]), "r"(a[2]), "r"(a[3]), "r"(b[0]), "r"(b[1]));
}

__device__ __forceinline__ void ldsm4(uint32_t* r, const void* p) {
    uint32_t a = (uint32_t)__cvta_generic_to_shared(p);
    asm volatile("ldmatrix.sync.aligned.m8n8.x4.shared.b16 {%0,%1,%2,%3}, [%4];"
                 : "=r"(r[0]), "=r"(r[1]), "=r"(r[2]), "=r"(r[3]) : "r"(a));
}

__device__ __forceinline__ void cp_async16(void* smem_dst, const void* gsrc) {
    uint32_t a = (uint32_t)__cvta_generic_to_shared(smem_dst);
    asm volatile("cp.async.cg.shared.global [%0], [%1], 16;" :: "r"(a), "l"(gsrc));
}
#define CP_COMMIT() asm volatile("cp.async.commit_group;" ::: "memory")
#define CP_WAIT(n)  asm volatile("cp.async.wait_group %0;" :: "n"(n) : "memory")

__device__ __forceinline__ uint32_t pack_h2(float a, float b) {
    __half2 h = __floats2half2_rn(a, b);
    return *(uint32_t*)&h;
}

// ---------------------------------------------------------------------------
// Fused pre-round pass: fp32 -> fp16 copies of hs / w_in / w_out
// ---------------------------------------------------------------------------
#define NX4  (MM * HH / 4)
#define NWI4 (K3H * HH / 4)
#define NWO4 (HH * HH / 4)
__global__ void round_all(const float4* __restrict__ hs,
                          const float4* __restrict__ wi,
                          const float4* __restrict__ wo)
{
    const int i = blockIdx.x * blockDim.x + threadIdx.x;
    const float4* src;
    __half* dst;
    int off;
    if (i < NX4)              { src = hs; dst = g_x;  off = i; }
    else if (i < NX4 + NWI4)  { src = wi; dst = g_wi; off = i - NX4; }
    else                      { src = wo; dst = g_wo; off = i - NX4 - NWI4; }
    float4 v = src[off];
    uint2 u = make_uint2(pack_h2(v.x, v.y), pack_h2(v.z, v.w));
    *(uint2*)(dst + (long)off * 4) = u;
}

// ---------------------------------------------------------------------------
// fp16 m16n8k16 GEMM: KCH=64 chunks (128B rows), 3-stage cp.async(.cg),
// XOR swizzle u^(row&7), depth-1 fragment pipeline over 4 k16-steps.
// MODE 0: A=g_x, B=g_wi; scatter -> g_q/g_k (s-major), g_v (d-major).
// MODE 1: A=g_o, B=g_wo; Y = C + bias (fp32 out).
// ---------------------------------------------------------------------------
template <int MODE>
__global__ void __launch_bounds__(256, 2)
gemm_mma(const float* __restrict__ bias, float* __restrict__ Y)
{
    extern __shared__ __half smh[];
    // A stage s: smh + s*TILE_H ; B stage s: smh + (NSTAGE+s)*TILE_H

    const __half* Aptr = (MODE == 1) ? (const __half*)g_o : (const __half*)g_x;
    const __half* Bptr = (MODE == 1) ? (const __half*)g_wo : (const __half*)g_wi;

    const int t    = threadIdx.x;
    const int wid  = t >> 5;
    const int lane = t & 31;
    const int g    = lane >> 2;
    const int c    = lane & 3;
    const int wm   = (wid >> 2) * 64;
    const int wn   = (wid & 3) * 32;
    const int m0   = blockIdx.y * MT;
    const int n0   = blockIdx.x * NT;

    // ldmatrix lane mappings
    const int a_row = ((lane >> 3) & 1) * 8 + (lane & 7);
    const int a_q   = lane >> 4;                 // 16B unit within k16
    const int b_row = ((lane >> 4) & 1) * 8 + (lane & 7);
    const int b_q   = (lane >> 3) & 1;
    const int swb   = lane & 7;                  // row&7 for both (tile bases mult of 8)

    // cp.async mapping: row = t>>1 (0..127), units q = (t&1)*4 + j (j=0..3)
    const int lrow = t >> 1;
    const int q0w  = (t & 1) * 4;
    const int rsw  = lrow & 7;
    const __half* Ag = Aptr + (long)(m0 + lrow) * HH;
    const __half* Bg = Bptr + (long)(n0 + lrow) * HH;
    __half* AsRow = smh + lrow * KCH;
    __half* BsRow = smh + NSTAGE * TILE_H + lrow * KCH;

    float acc[4][4][4];
#pragma unroll
    for (int mi = 0; mi < 4; mi++)
#pragma unroll
        for (int ni = 0; ni < 4; ni++)
#pragma unroll
            for (int k = 0; k < 4; k++) acc[mi][ni][k] = 0.f;

#pragma unroll
    for (int s = 0; s < 2; s++) {
#pragma unroll
        for (int j = 0; j < 4; j++) {
            const int q  = q0w + j;
            const int sq = (q ^ rsw) * 8;
            cp_async16(AsRow + s * TILE_H + sq, Ag + s * KCH + q * 8);
            cp_async16(BsRow + s * TILE_H + sq, Bg + s * KCH + q * 8);
        }
        CP_COMMIT();
    }

    int st = 0, sf = 2;
#pragma unroll 1
    for (int kt = 0; kt < NCHUNK; kt++) {
        CP_WAIT(1);
        __syncthreads();

        if (kt + 2 < NCHUNK) {
#pragma unroll
            for (int j = 0; j < 4; j++) {
                const int q  = q0w + j;
                const int sq = (q ^ rsw) * 8;
                cp_async16(AsRow + sf * TILE_H + sq, Ag + (kt + 2) * KCH + q * 8);
                cp_async16(BsRow + sf * TILE_H + sq, Bg + (kt + 2) * KCH + q * 8);
            }
            CP_COMMIT();
        }

        const __half* As = smh + st * TILE_H;
        const __half* Bs = smh + (NSTAGE + st) * TILE_H;

        // 4 k16-steps, depth-1 fragment pipeline
        uint32_t af[2][4][4], bf[2][2][4];
        {
            const int ua = ((0 + a_q) ^ swb) * 8;
            const int ub = ((0 + b_q) ^ swb) * 8;
#pragma unroll
            for (int mi = 0; mi < 4; mi++)
                ldsm4(af[0][mi], As + (wm + mi * 16 + a_row) * KCH + ua);
            ldsm4(bf[0][0], Bs + (wn + b_row) * KCH + ub);
            ldsm4(bf[0][1], Bs + (wn + 16 + b_row) * KCH + ub);
        }
#pragma unroll
        for (int ks = 0; ks < 4; ks++) {
            const int cur = ks & 1, nxt = cur ^ 1;
            if (ks < 3) {
                const int ua = ((2 * (ks + 1) + a_q) ^ swb) * 8;
                const int ub = ((2 * (ks + 1) + b_q) ^ swb) * 8;
#pragma unroll
                for (int mi = 0; mi < 4; mi++)
                    ldsm4(af[nxt][mi], As + (wm + mi * 16 + a_row) * KCH + ua);
                ldsm4(bf[nxt][0], Bs + (wn + b_row) * KCH + ub);
                ldsm4(bf[nxt][1], Bs + (wn + 16 + b_row) * KCH + ub);
            }
#pragma unroll
            for (int mi = 0; mi < 4; mi++) {
                mma_f16(acc[mi][0], af[cur][mi], &bf[cur][0][0]);
                mma_f16(acc[mi][1], af[cur][mi], &bf[cur][0][2]);
                mma_f16(acc[mi][2], af[cur][mi], &bf[cur][1][0]);
                mma_f16(acc[mi][3], af[cur][mi], &bf[cur][1][2]);
            }
        }

        st = (st == NSTAGE - 1) ? 0 : st + 1;
        sf = (sf == NSTAGE - 1) ? 0 : sf + 1;
    }

    // Epilogue
#pragma unroll
    for (int ni = 0; ni < 4; ni++) {
        const int col = n0 + wn + ni * 8 + 2 * c;
        const float b0 = bias[col];
        const float b1 = bias[col + 1];
#pragma unroll
        for (int mi = 0; mi < 4; mi++) {
            const int r1 = m0 + wm + mi * 16 + g;
            const int r2 = r1 + 8;
            if (MODE == 0) {
                const int which = col >> 10;
                const int hn    = (col & 1023) >> 6;
                const int d     = col & 63;
                const float scale = (which == 0) ? 0.125f : 1.0f;
                const int bb1 = r1 >> 11, s1 = r1 & 2047;
                const int bb2 = r2 >> 11, s2 = r2 & 2047;
                uint32_t v1 = pack_h2((acc[mi][ni][0] + b0) * scale,
                                      (acc[mi][ni][1] + b1) * scale);
                uint32_t v2 = pack_h2((acc[mi][ni][2] + b0) * scale,
                                      (acc[mi][ni][3] + b1) * scale);
                if (which == 2) {
                    __half* p1 = g_v + ((long)(bb1 * NH + hn) * DD + d) * SS + s1;
                    __half* p2 = g_v + ((long)(bb2 * NH + hn) * DD + d) * SS + s2;
                    __half2 h1 = *(__half2*)&v1;
                    __half2 h2 = *(__half2*)&v2;
                    p1[0] = __low2half(h1);  p1[SS] = __high2half(h1);
                    p2[0] = __low2half(h2);  p2[SS] = __high2half(h2);
                } else {
                    __half* dst0 = (which == 0) ? g_q : g_k;
                    *(uint32_t*)(dst0 + (((long)(bb1 * NH + hn) * SS) + s1) * DD + d) = v1;
                    *(uint32_t*)(dst0 + (((long)(bb2 * NH + hn) * SS) + s2) * DD + d) = v2;
                }
            } else {
                *(float2*)(Y + (long)r1 * HH + col) =
                    make_float2(acc[mi][ni][0] + b0, acc[mi][ni][1] + b1);
                *(float2*)(Y + (long)r2 * HH + col) =
                    make_float2(acc[mi][ni][2] + b0, acc[mi][ni][3] + b1);
            }
        }
    }
}

// ---------------------------------------------------------------------------
// Kernel 2: causal flash attention, fp16 m16n8k16, heavy-first CTA order.
// ---------------------------------------------------------------------------
__global__ void __launch_bounds__(256, 2) flash_attn_mma()
{
    __shared__ __half Ks[32][64];    // [kv][d], XOR-swizzled u^(row&7)
    __shared__ __half Vs[32][64];    // packed [d-pair][...], swizzled
    __shared__ __half Ps[128][40];   // [qrow][kv], pad 40 (80B stride)

    const int t    = threadIdx.x;
    const int wid  = t >> 5;
    const int lane = t & 31;
    const int g    = lane >> 2;
    const int c    = lane & 3;
    const int bn   = blockIdx.y;
    const int q0   = (gridDim.x - 1 - blockIdx.x) * 128;
    const int wr   = wid * 16;

    const int a_row = ((lane >> 3) & 1) * 8 + (lane & 7);
    const int a_kof = (lane >> 4) * 8;              // halves
    const int b_row = ((lane >> 4) & 1) * 8 + (lane & 7);
    const int b_q   = (lane >> 3) & 1;
    const int b_swb = lane & 7;
    // V (packed-pair) mapping constants
    const int vpr   = ((lane >> 4) & 1) * 4 + ((lane & 7) >> 1);  // prow within 8
    const int v_hi  = (lane & 1) << 2;

    const __half* Qp = g_q + (long)bn * SS * DD;
    const __half* Kp = g_k + (long)bn * SS * DD;
    const __half* Vp = g_v + (long)bn * DD * SS;

    // K load slots: row = t>>3 (32 rows), unit u = t&7 (8 x 16B)
    const int k_row = t >> 3;
    const int k_u   = t & 7;
    const int k_us  = (k_u ^ (k_row & 7)) * 8;      // halves
    // V load slots: d = t>>2 (64), unit u = t&3 (4 x 16B of kv)
    const int v_d   = t >> 2;
    const int v_u   = t & 3;
    const int v_pr  = v_d >> 1;
    const int v_us  = ((((v_d & 1) << 2) | v_u) ^ (v_pr & 7)) * 8;

    // Q fragments (fp16 pairs), loaded once: 4 k16-steps
    uint32_t Qf[4][4];
    {
        const __half* qr0 = Qp + (long)(q0 + wr + g) * DD;
        const __half* qr1 = qr0 + 8 * DD;
#pragma unroll
        for (int ks = 0; ks < 4; ks++) {
            Qf[ks][0] = *(const uint32_t*)(qr0 + ks * 16 + 2 * c);
            Qf[ks][1] = *(const uint32_t*)(qr1 + ks * 16 + 2 * c);
            Qf[ks][2] = *(const uint32_t*)(qr0 + ks * 16 + 2 * c + 8);
            Qf[ks][3] = *(const uint32_t*)(qr1 + ks * 16 + 2 * c + 8);
        }
    }

    float O[8][4];
#pragma unroll
    for (int dn = 0; dn < 8; dn++)
#pragma unroll
        for (int k = 0; k < 4; k++) O[dn][k] = 0.f;
    float m0v = -1e30f, m1v = -1e30f, l0 = 0.f, l1 = 0.f;

    const int r0g = q0 + wr + g;
    const int r1g = r0g + 8;
    const int nkt = (q0 + 128) >> 5;

    float4 ka, va;
    ka = *(const float4*)(Kp + (long)k_row * DD + k_u * 8);
    va = *(const float4*)(Vp + (long)v_d * SS + v_u * 8);

    for (int kt = 0; kt < nkt; kt++) {
        const int k0 = kt * 32;
        __syncthreads();
        *(float4*)&Ks[k_row][k_us] = ka;
        *(float4*)&Vs[v_pr][v_us]  = va;
        __syncthreads();

        if (kt + 1 < nkt) {
            const int kn = k0 + 32;
            ka = *(const float4*)(Kp + (long)(kn + k_row) * DD + k_u * 8);
            va = *(const float4*)(Vp + (long)v_d * SS + kn + v_u * 8);
        }

        // ---- S = Q K^T : 4 k16-steps, 2 ldsm4 + 4 MMAs each ----
        float S[4][4];
#pragma unroll
        for (int ni = 0; ni < 4; ni++)
#pragma unroll
            for (int k = 0; k < 4; k++) S[ni][k] = 0.f;
#pragma unroll
        for (int ks = 0; ks < 4; ks++) {
            const int u = ((2 * ks + b_q) ^ b_swb) * 8;
            uint32_t bt[4];
            ldsm4(bt, &Ks[b_row][u]);
            mma_f16(S[0], Qf[ks], &bt[0]);
            mma_f16(S[1], Qf[ks], &bt[2]);
            ldsm4(bt, &Ks[16 + b_row][u]);
            mma_f16(S[2], Qf[ks], &bt[0]);
            mma_f16(S[3], Qf[ks], &bt[2]);
        }

        // causal mask + online softmax (fp32)
        float mx0 = m0v, mx1 = m1v;
#pragma unroll
        for (int ni = 0; ni < 4; ni++) {
            const int col0 = k0 + ni * 8 + 2 * c;
            const int col1 = col0 + 1;
            if (col0 > r0g) S[ni][0] = -1e30f;
            if (col1 > r0g) S[ni][1] = -1e30f;
            if (col0 > r1g) S[ni][2] = -1e30f;
            if (col1 > r1g) S[ni][3] = -1e30f;
            mx0 = fmaxf(mx0, fmaxf(S[ni][0], S[ni][1]));
            mx1 = fmaxf(mx1, fmaxf(S[ni][2], S[ni][3]));
        }
        mx0 = fmaxf(mx0, __shfl_xor_sync(0xffffffffu, mx0, 1));
        mx0 = fmaxf(mx0, __shfl_xor_sync(0xffffffffu, mx0, 2));
        mx1 = fmaxf(mx1, __shfl_xor_sync(0xffffffffu, mx1, 1));
        mx1 = fmaxf(mx1, __shfl_xor_sync(0xffffffffu, mx1, 2));

        const float a0 = __expf(m0v - mx0);
        const float a1 = __expf(m1v - mx1);
        m0v = mx0; m1v = mx1;

        float rs0 = 0.f, rs1 = 0.f;
#pragma unroll
        for (int ni = 0; ni < 4; ni++) {
            float p00 = __expf(S[ni][0] - mx0);
            float p01 = __expf(S[ni][1] - mx0);
            float p10 = __expf(S[ni][2] - mx1);
            float p11 = __expf(S[ni][3] - mx1);
            rs0 += p00 + p01; rs1 += p10 + p11;
            *(uint32_t*)&Ps[wr + g][ni * 8 + 2 * c]     = pack_h2(p00, p01);
            *(uint32_t*)&Ps[wr + g + 8][ni * 8 + 2 * c] = pack_h2(p10, p11);
        }
        rs0 += __shfl_xor_sync(0xffffffffu, rs0, 1);
        rs0 += __shfl_xor_sync(0xffffffffu, rs0, 2);
        rs1 += __shfl_xor_sync(0xffffffffu, rs1, 1);
        rs1 += __shfl_xor_sync(0xffffffffu, rs1, 2);
        l0 = l0 * a0 + rs0;
        l1 = l1 * a1 + rs1;

#pragma unroll
        for (int dn = 0; dn < 8; dn++) {
            O[dn][0] *= a0; O[dn][1] *= a0;
            O[dn][2] *= a1; O[dn][3] *= a1;
        }
        __syncwarp();

        // ---- O += P @ V : 2 k16-steps (kv 0-15, 16-31) ----
#pragma unroll
        for (int j = 0; j < 2; j++) {
            uint32_t Af[4];
            ldsm4(Af, &Ps[wr + a_row][j * 16 + a_kof]);
#pragma unroll
            for (int dnp = 0; dnp < 4; dnp++) {
                const int pu = ((v_hi | (2 * j + ((lane >> 3) & 1))) ^ vpr) * 8;
                uint32_t bt[4];
                ldsm4(bt, &Vs[dnp * 8 + vpr][pu]);
                mma_f16(O[dnp * 2 + 0], Af, &bt[0]);
                mma_f16(O[dnp * 2 + 1], Af, &bt[2]);
            }
        }
    }

    // epilogue: O /= l, write g_o (fp16)
    const float inv0 = 1.0f / l0;
    const float inv1 = 1.0f / l1;
    const int b  = bn >> 4;
    const int hn = bn & 15;
    __half* orow0 = g_o + (long)(b * SS + r0g) * HH + hn * DD;
    __half* orow1 = orow0 + 8 * HH;
#pragma unroll
    for (int dn = 0; dn < 8; dn++) {
        *(uint32_t*)(orow0 + dn * 8 + 2 * c) = pack_h2(O[dn][0] * inv0, O[dn][1] * inv0);
        *(uint32_t*)(orow1 + dn * 8 + 2 * c) = pack_h2(O[dn][2] * inv1, O[dn][3] * inv1);
    }
}

// ---------------------------------------------------------------------------
extern "C" void kernel_launch(void* const* d_in, const int* in_sizes, int n_in,
                              void* d_out, int out_size)
{
    const float* hs    = (const float*)d_in[0];  // [B,S,H]
    const float* w_in  = (const float*)d_in[1];  // [3H,H]
    const float* b_in  = (const float*)d_in[2];  // [3H]
    const float* w_out = (const float*)d_in[3];  // [H,H]
    const float* b_out = (const float*)d_in[4];  // [H]
    float* out = (float*)d_out;                  // [B,S,H]

    (void)in_sizes; (void)n_in; (void)out_size;

    cudaFuncSetAttribute(gemm_mma<0>, cudaFuncAttributeMaxDynamicSharedMemorySize, SMEM_DYN);
    cudaFuncSetAttribute(gemm_mma<1>, cudaFuncAttributeMaxDynamicSharedMemorySize, SMEM_DYN);

    round_all<<<(NX4 + NWI4 + NWO4) / 256, 256>>>(
        (const float4*)hs, (const float4*)w_in, (const float4*)w_out);

    gemm_mma<0><<<dim3(K3H / NT, MM / MT), 256, SMEM_DYN>>>(b_in, nullptr);
    flash_attn_mma<<<dim3(SS / 128, BB * NH), 256>>>();
    gemm_mma<1><<<dim3(HH / NT, MM / MT), 256, SMEM_DYN>>>(b_out, out);
}

// round 16
// speedup vs baseline: 1.8196x; 1.0570x over previous
#include <cuda_runtime.h>
#include <cuda_fp16.h>
#include <cstdint>

// Problem dims
#define BB 2
#define SS 2048
#define HH 1024
#define NH 16
#define DD 64
#define MM (BB * SS)       // 4096 rows
#define K3H (3 * HH)       // 3072

// GEMM tiling: 128x128 CTA, 8 warps, 64x32 warp tile, fp16 m16n8k16
#define MT 128
#define NT 128
#define KCH 64             // halves per k-chunk (128B rows)
#define NCHUNK (HH / KCH)  // 16
#define NSTAGE 3
#define TILE_H (MT * KCH)                   // 8192 halves = 16KB per tile
#define SMEM_DYN (2 * NSTAGE * TILE_H * 2)  // 98304 B

// Attention: BQ=128, BK=64, 2-stage cp.async K/V
#define AT_STG_H 4096                       // 64x64 halves per K or V stage
#define AT_PS_OFF 16384                     // halves offset of Ps
#define AT_SMEM (16384 * 2 + 128 * 72 * 2)  // 51200 B

// Scratch (device globals; no allocation allowed) -- all fp16
__device__ __half g_x [MM * HH];
__device__ __half g_wi[K3H * HH];
__device__ __half g_wo[HH * HH];
__device__ __half g_q[BB * NH * SS * DD];   // [b][n][s][d], scaled
__device__ __half g_k[BB * NH * SS * DD];   // [b][n][s][d]
__device__ __half g_v[BB * NH * DD * SS];   // [b][n][d][s]
__device__ __half g_o[MM * HH];             // [b*s][h]

__device__ __forceinline__ void mma_f16(float* d, const uint32_t* a, const uint32_t* b) {
    asm volatile(
        "mma.sync.aligned.m16n8k16.row.col.f32.f16.f16.f32 "
        "{%0,%1,%2,%3}, {%4,%5,%6,%7}, {%8,%9}, {%0,%1,%2,%3};"
        : "+f"(d[0]), "+f"(d[1]), "+f"(d[2]), "+f"(d[3])
        : "r"(a[0]), "r"(a[1]), "r"(a[2]), "r"(a[3]), "r"(b[0]), "r"(b[1]));
}

__device__ __forceinline__ void ldsm4(uint32_t* r, const void* p) {
    uint32_t a = (uint32_t)__cvta_generic_to_shared(p);
    asm volatile("ldmatrix.sync.aligned.m8n8.x4.shared.b16 {%0,%1,%2,%3}, [%4];"
                 : "=r"(r[0]), "=r"(r[1]), "=r"(r[2]), "=r"(r[3]) : "r"(a));
}

__device__ __forceinline__ void cp_async16(void* smem_dst, const void* gsrc) {
    uint32_t a = (uint32_t)__cvta_generic_to_shared(smem_dst);
    asm volatile("cp.async.cg.shared.global [%0], [%1], 16;" :: "r"(a), "l"(gsrc));
}
#define CP_COMMIT() asm volatile("cp.async.commit_group;" ::: "memory")
#define CP_WAIT(n)  asm volatile("cp.async.wait_group %0;" :: "n"(n) : "memory")

__device__ __forceinline__ uint32_t pack_h2(float a, float b) {
    __half2 h = __floats2half2_rn(a, b);
    return *(uint32_t*)&h;
}

// ---------------------------------------------------------------------------
// Fused pre-round pass: fp32 -> fp16 copies of hs / w_in / w_out
// ---------------------------------------------------------------------------
#define NX4  (MM * HH / 4)
#define NWI4 (K3H * HH / 4)
#define NWO4 (HH * HH / 4)
__global__ void round_all(const float4* __restrict__ hs,
                          const float4* __restrict__ wi,
                          const float4* __restrict__ wo)
{
    const int i = blockIdx.x * blockDim.x + threadIdx.x;
    const float4* src;
    __half* dst;
    int off;
    if (i < NX4)              { src = hs; dst = g_x;  off = i; }
    else if (i < NX4 + NWI4)  { src = wi; dst = g_wi; off = i - NX4; }
    else                      { src = wo; dst = g_wo; off = i - NX4 - NWI4; }
    float4 v = src[off];
    uint2 u = make_uint2(pack_h2(v.x, v.y), pack_h2(v.z, v.w));
    *(uint2*)(dst + (long)off * 4) = u;
}

// ---------------------------------------------------------------------------
// fp16 m16n8k16 GEMM (unchanged from R14 / known-good)
// ---------------------------------------------------------------------------
template <int MODE>
__global__ void __launch_bounds__(256, 2)
gemm_mma(const float* __restrict__ bias, float* __restrict__ Y)
{
    extern __shared__ __half smh[];

    const __half* Aptr = (MODE == 1) ? (const __half*)g_o : (const __half*)g_x;
    const __half* Bptr = (MODE == 1) ? (const __half*)g_wo : (const __half*)g_wi;

    const int t    = threadIdx.x;
    const int wid  = t >> 5;
    const int lane = t & 31;
    const int g    = lane >> 2;
    const int c    = lane & 3;
    const int wm   = (wid >> 2) * 64;
    const int wn   = (wid & 3) * 32;
    const int m0   = blockIdx.y * MT;
    const int n0   = blockIdx.x * NT;

    const int a_row = ((lane >> 3) & 1) * 8 + (lane & 7);
    const int a_q   = lane >> 4;
    const int b_row = ((lane >> 4) & 1) * 8 + (lane & 7);
    const int b_q   = (lane >> 3) & 1;
    const int swb   = lane & 7;

    const int lrow = t >> 1;
    const int q0w  = (t & 1) * 4;
    const int rsw  = lrow & 7;
    const __half* Ag = Aptr + (long)(m0 + lrow) * HH;
    const __half* Bg = Bptr + (long)(n0 + lrow) * HH;
    __half* AsRow = smh + lrow * KCH;
    __half* BsRow = smh + NSTAGE * TILE_H + lrow * KCH;

    float acc[4][4][4];
#pragma unroll
    for (int mi = 0; mi < 4; mi++)
#pragma unroll
        for (int ni = 0; ni < 4; ni++)
#pragma unroll
            for (int k = 0; k < 4; k++) acc[mi][ni][k] = 0.f;

#pragma unroll
    for (int s = 0; s < 2; s++) {
#pragma unroll
        for (int j = 0; j < 4; j++) {
            const int q  = q0w + j;
            const int sq = (q ^ rsw) * 8;
            cp_async16(AsRow + s * TILE_H + sq, Ag + s * KCH + q * 8);
            cp_async16(BsRow + s * TILE_H + sq, Bg + s * KCH + q * 8);
        }
        CP_COMMIT();
    }

    int st = 0, sf = 2;
#pragma unroll 1
    for (int kt = 0; kt < NCHUNK; kt++) {
        CP_WAIT(1);
        __syncthreads();

        if (kt + 2 < NCHUNK) {
#pragma unroll
            for (int j = 0; j < 4; j++) {
                const int q  = q0w + j;
                const int sq = (q ^ rsw) * 8;
                cp_async16(AsRow + sf * TILE_H + sq, Ag + (kt + 2) * KCH + q * 8);
                cp_async16(BsRow + sf * TILE_H + sq, Bg + (kt + 2) * KCH + q * 8);
            }
            CP_COMMIT();
        }

        const __half* As = smh + st * TILE_H;
        const __half* Bs = smh + (NSTAGE + st) * TILE_H;

        uint32_t af[2][4][4], bf[2][2][4];
        {
            const int ua = ((0 + a_q) ^ swb) * 8;
            const int ub = ((0 + b_q) ^ swb) * 8;
#pragma unroll
            for (int mi = 0; mi < 4; mi++)
                ldsm4(af[0][mi], As + (wm + mi * 16 + a_row) * KCH + ua);
            ldsm4(bf[0][0], Bs + (wn + b_row) * KCH + ub);
            ldsm4(bf[0][1], Bs + (wn + 16 + b_row) * KCH + ub);
        }
#pragma unroll
        for (int ks = 0; ks < 4; ks++) {
            const int cur = ks & 1, nxt = cur ^ 1;
            if (ks < 3) {
                const int ua = ((2 * (ks + 1) + a_q) ^ swb) * 8;
                const int ub = ((2 * (ks + 1) + b_q) ^ swb) * 8;
#pragma unroll
                for (int mi = 0; mi < 4; mi++)
                    ldsm4(af[nxt][mi], As + (wm + mi * 16 + a_row) * KCH + ua);
                ldsm4(bf[nxt][0], Bs + (wn + b_row) * KCH + ub);
                ldsm4(bf[nxt][1], Bs + (wn + 16 + b_row) * KCH + ub);
            }
#pragma unroll
            for (int mi = 0; mi < 4; mi++) {
                mma_f16(acc[mi][0], af[cur][mi], &bf[cur][0][0]);
                mma_f16(acc[mi][1], af[cur][mi], &bf[cur][0][2]);
                mma_f16(acc[mi][2], af[cur][mi], &bf[cur][1][0]);
                mma_f16(acc[mi][3], af[cur][mi], &bf[cur][1][2]);
            }
        }

        st = (st == NSTAGE - 1) ? 0 : st + 1;
        sf = (sf == NSTAGE - 1) ? 0 : sf + 1;
    }

    // Epilogue
#pragma unroll
    for (int ni = 0; ni < 4; ni++) {
        const int col = n0 + wn + ni * 8 + 2 * c;
        const float b0 = bias[col];
        const float b1 = bias[col + 1];
#pragma unroll
        for (int mi = 0; mi < 4; mi++) {
            const int r1 = m0 + wm + mi * 16 + g;
            const int r2 = r1 + 8;
            if (MODE == 0) {
                const int which = col >> 10;
                const int hn    = (col & 1023) >> 6;
                const int d     = col & 63;
                const float scale = (which == 0) ? 0.125f : 1.0f;
                const int bb1 = r1 >> 11, s1 = r1 & 2047;
                const int bb2 = r2 >> 11, s2 = r2 & 2047;
                uint32_t v1 = pack_h2((acc[mi][ni][0] + b0) * scale,
                                      (acc[mi][ni][1] + b1) * scale);
                uint32_t v2 = pack_h2((acc[mi][ni][2] + b0) * scale,
                                      (acc[mi][ni][3] + b1) * scale);
                if (which == 2) {
                    __half* p1 = g_v + ((long)(bb1 * NH + hn) * DD + d) * SS + s1;
                    __half* p2 = g_v + ((long)(bb2 * NH + hn) * DD + d) * SS + s2;
                    __half2 h1 = *(__half2*)&v1;
                    __half2 h2 = *(__half2*)&v2;
                    p1[0] = __low2half(h1);  p1[SS] = __high2half(h1);
                    p2[0] = __low2half(h2);  p2[SS] = __high2half(h2);
                } else {
                    __half* dst0 = (which == 0) ? g_q : g_k;
                    *(uint32_t*)(dst0 + (((long)(bb1 * NH + hn) * SS) + s1) * DD + d) = v1;
                    *(uint32_t*)(dst0 + (((long)(bb2 * NH + hn) * SS) + s2) * DD + d) = v2;
                }
            } else {
                *(float2*)(Y + (long)r1 * HH + col) =
                    make_float2(acc[mi][ni][0] + b0, acc[mi][ni][1] + b1);
                *(float2*)(Y + (long)r2 * HH + col) =
                    make_float2(acc[mi][ni][2] + b0, acc[mi][ni][3] + b1);
            }
        }
    }
}

// ---------------------------------------------------------------------------
// Kernel 2: causal flash attention, fp16 m16n8k16, BK=64, 2-stage cp.async
// K/V (plain XOR swizzle on 128B rows), heavy-first CTA order.
// SMEM (halves): Ks stage s @ s*4096 ; Vs stage s @ 8192+s*4096 ; Ps @ 16384.
// ---------------------------------------------------------------------------
__global__ void __launch_bounds__(256, 2) flash_attn_mma()
{
    extern __shared__ __half smh[];
    __half* Psb = smh + AT_PS_OFF;          // [128][72]

    const int t    = threadIdx.x;
    const int wid  = t >> 5;
    const int lane = t & 31;
    const int g    = lane >> 2;
    const int c    = lane & 3;
    const int bn   = blockIdx.y;
    const int q0   = (gridDim.x - 1 - blockIdx.x) * 128;   // heavy tiles first
    const int wr   = wid * 16;

    const int a_row = ((lane >> 3) & 1) * 8 + (lane & 7);
    const int a_kof = (lane >> 4) * 8;              // halves
    const int b_row = ((lane >> 4) & 1) * 8 + (lane & 7);
    const int b_q   = (lane >> 3) & 1;
    const int b_swb = b_row & 7;

    const __half* Qp = g_q + (long)bn * SS * DD;
    const __half* Kp = g_k + (long)bn * SS * DD;
    const __half* Vp = g_v + (long)bn * DD * SS;

    // K/V load slots: slot = t + p*256 ; row = slot>>3 (64), u = slot&7
    const int l_row0 = t >> 3;              // rows t>>3 and t>>3 + 32
    const int l_u    = t & 7;

    // Q fragments, loaded once (4 k16-steps over d)
    uint32_t Qf[4][4];
    {
        const __half* qr0 = Qp + (long)(q0 + wr + g) * DD;
        const __half* qr1 = qr0 + 8 * DD;
#pragma unroll
        for (int ks = 0; ks < 4; ks++) {
            Qf[ks][0] = *(const uint32_t*)(qr0 + ks * 16 + 2 * c);
            Qf[ks][1] = *(const uint32_t*)(qr1 + ks * 16 + 2 * c);
            Qf[ks][2] = *(const uint32_t*)(qr0 + ks * 16 + 2 * c + 8);
            Qf[ks][3] = *(const uint32_t*)(qr1 + ks * 16 + 2 * c + 8);
        }
    }

    float O[8][4];
#pragma unroll
    for (int dn = 0; dn < 8; dn++)
#pragma unroll
        for (int k = 0; k < 4; k++) O[dn][k] = 0.f;
    float m0v = -1e30f, m1v = -1e30f, l0 = 0.f, l1 = 0.f;

    const int r0g = q0 + wr + g;
    const int r1g = r0g + 8;
    const int nkt = (q0 + 128) >> 6;        // BK=64 tiles up to diagonal

    // prologue: tile 0 -> stage 0
#pragma unroll
    for (int p = 0; p < 2; p++) {
        const int row = l_row0 + p * 32;
        const int sc  = ((l_u ^ (row & 7)) * 8);
        cp_async16(smh + row * 64 + sc,        Kp + (long)row * DD + l_u * 8);
        cp_async16(smh + 8192 + row * 64 + sc, Vp + (long)row * SS + l_u * 8);
    }
    CP_COMMIT();

    for (int kt = 0; kt < nkt; kt++) {
        const int k0 = kt * 64;
        const int st = kt & 1;

        if (kt + 1 < nkt) {
            const int kn = k0 + 64;
            const int sn = st ^ 1;
#pragma unroll
            for (int p = 0; p < 2; p++) {
                const int row = l_row0 + p * 32;
                const int sc  = ((l_u ^ (row & 7)) * 8);
                cp_async16(smh + sn * AT_STG_H + row * 64 + sc,
                           Kp + (long)(kn + row) * DD + l_u * 8);
                cp_async16(smh + 8192 + sn * AT_STG_H + row * 64 + sc,
                           Vp + (long)row * SS + kn + l_u * 8);
            }
            CP_COMMIT();
            CP_WAIT(1);
        } else {
            CP_WAIT(0);
        }
        __syncthreads();

        const __half* Ks = smh + st * AT_STG_H;
        const __half* Vs = smh + 8192 + st * AT_STG_H;

        // ---- S = Q K^T : 4 k16-steps x 4 kv-blocks ----
        float S[8][4];
#pragma unroll
        for (int ni = 0; ni < 8; ni++)
#pragma unroll
            for (int k = 0; k < 4; k++) S[ni][k] = 0.f;
#pragma unroll
        for (int ks = 0; ks < 4; ks++) {
            const int u = ((2 * ks + b_q) ^ b_swb) * 8;
#pragma unroll
            for (int nb = 0; nb < 4; nb++) {
                uint32_t bt[4];
                ldsm4(bt, Ks + (nb * 16 + b_row) * 64 + u);
                mma_f16(S[nb * 2 + 0], Qf[ks], &bt[0]);
                mma_f16(S[nb * 2 + 1], Qf[ks], &bt[2]);
            }
        }

        // causal mask + online softmax
        float mx0 = m0v, mx1 = m1v;
#pragma unroll
        for (int ni = 0; ni < 8; ni++) {
            const int col0 = k0 + ni * 8 + 2 * c;
            const int col1 = col0 + 1;
            if (col0 > r0g) S[ni][0] = -1e30f;
            if (col1 > r0g) S[ni][1] = -1e30f;
            if (col0 > r1g) S[ni][2] = -1e30f;
            if (col1 > r1g) S[ni][3] = -1e30f;
            mx0 = fmaxf(mx0, fmaxf(S[ni][0], S[ni][1]));
            mx1 = fmaxf(mx1, fmaxf(S[ni][2], S[ni][3]));
        }
        mx0 = fmaxf(mx0, __shfl_xor_sync(0xffffffffu, mx0, 1));
        mx0 = fmaxf(mx0, __shfl_xor_sync(0xffffffffu, mx0, 2));
        mx1 = fmaxf(mx1, __shfl_xor_sync(0xffffffffu, mx1, 1));
        mx1 = fmaxf(mx1, __shfl_xor_sync(0xffffffffu, mx1, 2));

        const float a0 = __expf(m0v - mx0);
        const float a1 = __expf(m1v - mx1);
        m0v = mx0; m1v = mx1;

        float rs0 = 0.f, rs1 = 0.f;
#pragma unroll
        for (int ni = 0; ni < 8; ni++) {
            float p00 = __expf(S[ni][0] - mx0);
            float p01 = __expf(S[ni][1] - mx0);
            float p10 = __expf(S[ni][2] - mx1);
            float p11 = __expf(S[ni][3] - mx1);
            rs0 += p00 + p01; rs1 += p10 + p11;
            *(uint32_t*)(Psb + (wr + g) * 72 + ni * 8 + 2 * c)     = pack_h2(p00, p01);
            *(uint32_t*)(Psb + (wr + g + 8) * 72 + ni * 8 + 2 * c) = pack_h2(p10, p11);
        }
        rs0 += __shfl_xor_sync(0xffffffffu, rs0, 1);
        rs0 += __shfl_xor_sync(0xffffffffu, rs0, 2);
        rs1 += __shfl_xor_sync(0xffffffffu, rs1, 1);
        rs1 += __shfl_xor_sync(0xffffffffu, rs1, 2);
        l0 = l0 * a0 + rs0;
        l1 = l1 * a1 + rs1;

#pragma unroll
        for (int dn = 0; dn < 8; dn++) {
            O[dn][0] *= a0; O[dn][1] *= a0;
            O[dn][2] *= a1; O[dn][3] *= a1;
        }
        __syncwarp();   // order Ps stores before ldmatrix reads (warp-private rows)

        // ---- O += P @ V : 4 k16-steps over kv ----
#pragma unroll
        for (int j = 0; j < 4; j++) {
            uint32_t Af[4];
            ldsm4(Af, Psb + (wr + a_row) * 72 + j * 16 + a_kof);
            const int u = ((2 * j + b_q) ^ b_swb) * 8;
#pragma unroll
            for (int dnp = 0; dnp < 4; dnp++) {
                uint32_t bt[4];
                ldsm4(bt, Vs + (dnp * 16 + b_row) * 64 + u);
                mma_f16(O[dnp * 2 + 0], Af, &bt[0]);
                mma_f16(O[dnp * 2 + 1], Af, &bt[2]);
            }
        }
        __syncthreads();   // compute done before next iter overwrites stage st
    }

    // epilogue: O /= l, write g_o (fp16)
    const float inv0 = 1.0f / l0;
    const float inv1 = 1.0f / l1;
    const int b  = bn >> 4;
    const int hn = bn & 15;
    __half* orow0 = g_o + (long)(b * SS + r0g) * HH + hn * DD;
    __half* orow1 = orow0 + 8 * HH;
#pragma unroll
    for (int dn = 0; dn < 8; dn++) {
        *(uint32_t*)(orow0 + dn * 8 + 2 * c) = pack_h2(O[dn][0] * inv0, O[dn][1] * inv0);
        *(uint32_t*)(orow1 + dn * 8 + 2 * c) = pack_h2(O[dn][2] * inv1, O[dn][3] * inv1);
    }
}

// ---------------------------------------------------------------------------
extern "C" void kernel_launch(void* const* d_in, const int* in_sizes, int n_in,
                              void* d_out, int out_size)
{
    const float* hs    = (const float*)d_in[0];  // [B,S,H]
    const float* w_in  = (const float*)d_in[1];  // [3H,H]
    const float* b_in  = (const float*)d_in[2];  // [3H]
    const float* w_out = (const float*)d_in[3];  // [H,H]
    const float* b_out = (const float*)d_in[4];  // [H]
    float* out = (float*)d_out;                  // [B,S,H]

    (void)in_sizes; (void)n_in; (void)out_size;

    cudaFuncSetAttribute(gemm_mma<0>, cudaFuncAttributeMaxDynamicSharedMemorySize, SMEM_DYN);
    cudaFuncSetAttribute(gemm_mma<1>, cudaFuncAttributeMaxDynamicSharedMemorySize, SMEM_DYN);
    cudaFuncSetAttribute(flash_attn_mma, cudaFuncAttributeMaxDynamicSharedMemorySize, AT_SMEM);

    round_all<<<(NX4 + NWI4 + NWO4) / 256, 256>>>(
        (const float4*)hs, (const float4*)w_in, (const float4*)w_out);

    gemm_mma<0><<<dim3(K3H / NT, MM / MT), 256, SMEM_DYN>>>(b_in, nullptr);
    flash_attn_mma<<<dim3(SS / 128, BB * NH), 256, AT_SMEM>>>();
    gemm_mma<1><<<dim3(HH / NT, MM / MT), 256, SMEM_DYN>>>(b_out, out);
}

// round 17
// speedup vs baseline: 1.8848x; 1.0358x over previous
#include <cuda_runtime.h>
#include <cuda_fp16.h>
#include <cstdint>

// Problem dims
#define BB 2
#define SS 2048
#define HH 1024
#define NH 16
#define DD 64
#define MM (BB * SS)       // 4096 rows
#define K3H (3 * HH)       // 3072

// GEMM tiling: 128x128 CTA, 8 warps, 64x32 warp tile, fp16 m16n8k16
#define MT 128
#define NT 128
#define KCH 64             // halves per k-chunk (128B rows)
#define NCHUNK (HH / KCH)  // 16
#define NSTAGE 3
#define TILE_H (MT * KCH)                   // 8192 halves = 16KB per tile
#define SMEM_DYN (2 * NSTAGE * TILE_H * 2)  // 98304 B

// Attention: BQ=128, BK=64, 2-stage cp.async K/V
#define AT_STG_H 4096                       // 64x64 halves per K or V stage
#define AT_PS_OFF 16384                     // halves offset of Ps
#define AT_SMEM (16384 * 2 + 128 * 72 * 2)  // 51200 B

// log2(e): scores computed in log2 domain so softmax uses bare exp2f (MUFU only)
#define QSCALE (0.125f * 1.44269504088896f)

// Scratch (device globals; no allocation allowed) -- all fp16
__device__ __half g_x [MM * HH];
__device__ __half g_wi[K3H * HH];
__device__ __half g_wo[HH * HH];
__device__ __half g_q[BB * NH * SS * DD];   // [b][n][s][d], scaled by QSCALE
__device__ __half g_k[BB * NH * SS * DD];   // [b][n][s][d]
__device__ __half g_v[BB * NH * DD * SS];   // [b][n][d][s]
__device__ __half g_o[MM * HH];             // [b*s][h]

__device__ __forceinline__ void mma_f16(float* d, const uint32_t* a, const uint32_t* b) {
    asm volatile(
        "mma.sync.aligned.m16n8k16.row.col.f32.f16.f16.f32 "
        "{%0,%1,%2,%3}, {%4,%5,%6,%7}, {%8,%9}, {%0,%1,%2,%3};"
        : "+f"(d[0]), "+f"(d[1]), "+f"(d[2]), "+f"(d[3])
        : "r"(a[0]), "r"(a[1]), "r"(a[2]), "r"(a[3]), "r"(b[0]), "r"(b[1]));
}

__device__ __forceinline__ void ldsm4(uint32_t* r, const void* p) {
    uint32_t a = (uint32_t)__cvta_generic_to_shared(p);
    asm volatile("ldmatrix.sync.aligned.m8n8.x4.shared.b16 {%0,%1,%2,%3}, [%4];"
                 : "=r"(r[0]), "=r"(r[1]), "=r"(r[2]), "=r"(r[3]) : "r"(a));
}

__device__ __forceinline__ void cp_async16(void* smem_dst, const void* gsrc) {
    uint32_t a = (uint32_t)__cvta_generic_to_shared(smem_dst);
    asm volatile("cp.async.cg.shared.global [%0], [%1], 16;" :: "r"(a), "l"(gsrc));
}
#define CP_COMMIT() asm volatile("cp.async.commit_group;" ::: "memory")
#define CP_WAIT(n)  asm volatile("cp.async.wait_group %0;" :: "n"(n) : "memory")

__device__ __forceinline__ uint32_t pack_h2(float a, float b) {
    __half2 h = __floats2half2_rn(a, b);
    return *(uint32_t*)&h;
}

// ---------------------------------------------------------------------------
// Fused pre-round pass: fp32 -> fp16 copies of hs / w_in / w_out
// ---------------------------------------------------------------------------
#define NX4  (MM * HH / 4)
#define NWI4 (K3H * HH / 4)
#define NWO4 (HH * HH / 4)
__global__ void round_all(const float4* __restrict__ hs,
                          const float4* __restrict__ wi,
                          const float4* __restrict__ wo)
{
    const int i = blockIdx.x * blockDim.x + threadIdx.x;
    const float4* src;
    __half* dst;
    int off;
    if (i < NX4)              { src = hs; dst = g_x;  off = i; }
    else if (i < NX4 + NWI4)  { src = wi; dst = g_wi; off = i - NX4; }
    else                      { src = wo; dst = g_wo; off = i - NX4 - NWI4; }
    float4 v = src[off];
    uint2 u = make_uint2(pack_h2(v.x, v.y), pack_h2(v.z, v.w));
    *(uint2*)(dst + (long)off * 4) = u;
}

// ---------------------------------------------------------------------------
// fp16 m16n8k16 GEMM (structure unchanged; Q scale now folds log2e)
// ---------------------------------------------------------------------------
template <int MODE>
__global__ void __launch_bounds__(256, 2)
gemm_mma(const float* __restrict__ bias, float* __restrict__ Y)
{
    extern __shared__ __half smh[];

    const __half* Aptr = (MODE == 1) ? (const __half*)g_o : (const __half*)g_x;
    const __half* Bptr = (MODE == 1) ? (const __half*)g_wo : (const __half*)g_wi;

    const int t    = threadIdx.x;
    const int wid  = t >> 5;
    const int lane = t & 31;
    const int g    = lane >> 2;
    const int c    = lane & 3;
    const int wm   = (wid >> 2) * 64;
    const int wn   = (wid & 3) * 32;
    const int m0   = blockIdx.y * MT;
    const int n0   = blockIdx.x * NT;

    const int a_row = ((lane >> 3) & 1) * 8 + (lane & 7);
    const int a_q   = lane >> 4;
    const int b_row = ((lane >> 4) & 1) * 8 + (lane & 7);
    const int b_q   = (lane >> 3) & 1;
    const int swb   = lane & 7;

    const int lrow = t >> 1;
    const int q0w  = (t & 1) * 4;
    const int rsw  = lrow & 7;
    const __half* Ag = Aptr + (long)(m0 + lrow) * HH;
    const __half* Bg = Bptr + (long)(n0 + lrow) * HH;
    __half* AsRow = smh + lrow * KCH;
    __half* BsRow = smh + NSTAGE * TILE_H + lrow * KCH;

    float acc[4][4][4];
#pragma unroll
    for (int mi = 0; mi < 4; mi++)
#pragma unroll
        for (int ni = 0; ni < 4; ni++)
#pragma unroll
            for (int k = 0; k < 4; k++) acc[mi][ni][k] = 0.f;

#pragma unroll
    for (int s = 0; s < 2; s++) {
#pragma unroll
        for (int j = 0; j < 4; j++) {
            const int q  = q0w + j;
            const int sq = (q ^ rsw) * 8;
            cp_async16(AsRow + s * TILE_H + sq, Ag + s * KCH + q * 8);
            cp_async16(BsRow + s * TILE_H + sq, Bg + s * KCH + q * 8);
        }
        CP_COMMIT();
    }

    int st = 0, sf = 2;
#pragma unroll 1
    for (int kt = 0; kt < NCHUNK; kt++) {
        CP_WAIT(1);
        __syncthreads();

        if (kt + 2 < NCHUNK) {
#pragma unroll
            for (int j = 0; j < 4; j++) {
                const int q  = q0w + j;
                const int sq = (q ^ rsw) * 8;
                cp_async16(AsRow + sf * TILE_H + sq, Ag + (kt + 2) * KCH + q * 8);
                cp_async16(BsRow + sf * TILE_H + sq, Bg + (kt + 2) * KCH + q * 8);
            }
            CP_COMMIT();
        }

        const __half* As = smh + st * TILE_H;
        const __half* Bs = smh + (NSTAGE + st) * TILE_H;

        uint32_t af[2][4][4], bf[2][2][4];
        {
            const int ua = ((0 + a_q) ^ swb) * 8;
            const int ub = ((0 + b_q) ^ swb) * 8;
#pragma unroll
            for (int mi = 0; mi < 4; mi++)
                ldsm4(af[0][mi], As + (wm + mi * 16 + a_row) * KCH + ua);
            ldsm4(bf[0][0], Bs + (wn + b_row) * KCH + ub);
            ldsm4(bf[0][1], Bs + (wn + 16 + b_row) * KCH + ub);
        }
#pragma unroll
        for (int ks = 0; ks < 4; ks++) {
            const int cur = ks & 1, nxt = cur ^ 1;
            if (ks < 3) {
                const int ua = ((2 * (ks + 1) + a_q) ^ swb) * 8;
                const int ub = ((2 * (ks + 1) + b_q) ^ swb) * 8;
#pragma unroll
                for (int mi = 0; mi < 4; mi++)
                    ldsm4(af[nxt][mi], As + (wm + mi * 16 + a_row) * KCH + ua);
                ldsm4(bf[nxt][0], Bs + (wn + b_row) * KCH + ub);
                ldsm4(bf[nxt][1], Bs + (wn + 16 + b_row) * KCH + ub);
            }
#pragma unroll
            for (int mi = 0; mi < 4; mi++) {
                mma_f16(acc[mi][0], af[cur][mi], &bf[cur][0][0]);
                mma_f16(acc[mi][1], af[cur][mi], &bf[cur][0][2]);
                mma_f16(acc[mi][2], af[cur][mi], &bf[cur][1][0]);
                mma_f16(acc[mi][3], af[cur][mi], &bf[cur][1][2]);
            }
        }

        st = (st == NSTAGE - 1) ? 0 : st + 1;
        sf = (sf == NSTAGE - 1) ? 0 : sf + 1;
    }

    // Epilogue
#pragma unroll
    for (int ni = 0; ni < 4; ni++) {
        const int col = n0 + wn + ni * 8 + 2 * c;
        const float b0 = bias[col];
        const float b1 = bias[col + 1];
#pragma unroll
        for (int mi = 0; mi < 4; mi++) {
            const int r1 = m0 + wm + mi * 16 + g;
            const int r2 = r1 + 8;
            if (MODE == 0) {
                const int which = col >> 10;
                const int hn    = (col & 1023) >> 6;
                const int d     = col & 63;
                const float scale = (which == 0) ? QSCALE : 1.0f;
                const int bb1 = r1 >> 11, s1 = r1 & 2047;
                const int bb2 = r2 >> 11, s2 = r2 & 2047;
                uint32_t v1 = pack_h2((acc[mi][ni][0] + b0) * scale,
                                      (acc[mi][ni][1] + b1) * scale);
                uint32_t v2 = pack_h2((acc[mi][ni][2] + b0) * scale,
                                      (acc[mi][ni][3] + b1) * scale);
                if (which == 2) {
                    __half* p1 = g_v + ((long)(bb1 * NH + hn) * DD + d) * SS + s1;
                    __half* p2 = g_v + ((long)(bb2 * NH + hn) * DD + d) * SS + s2;
                    __half2 h1 = *(__half2*)&v1;
                    __half2 h2 = *(__half2*)&v2;
                    p1[0] = __low2half(h1);  p1[SS] = __high2half(h1);
                    p2[0] = __low2half(h2);  p2[SS] = __high2half(h2);
                } else {
                    __half* dst0 = (which == 0) ? g_q : g_k;
                    *(uint32_t*)(dst0 + (((long)(bb1 * NH + hn) * SS) + s1) * DD + d) = v1;
                    *(uint32_t*)(dst0 + (((long)(bb2 * NH + hn) * SS) + s2) * DD + d) = v2;
                }
            } else {
                *(float2*)(Y + (long)r1 * HH + col) =
                    make_float2(acc[mi][ni][0] + b0, acc[mi][ni][1] + b1);
                *(float2*)(Y + (long)r2 * HH + col) =
                    make_float2(acc[mi][ni][2] + b0, acc[mi][ni][3] + b1);
            }
        }
    }
}

// ---------------------------------------------------------------------------
// Kernel 2: causal flash attention, fp16 m16n8k16, BK=64, 2-stage cp.async.
// Softmax in exp2 domain (scores pre-scaled by log2e); causal mask applied
// only on diagonal-crossing tiles (warp-uniform fast path).
// ---------------------------------------------------------------------------
__global__ void __launch_bounds__(256, 2) flash_attn_mma()
{
    extern __shared__ __half smh[];
    __half* Psb = smh + AT_PS_OFF;          // [128][72]

    const int t    = threadIdx.x;
    const int wid  = t >> 5;
    const int lane = t & 31;
    const int g    = lane >> 2;
    const int c    = lane & 3;
    const int bn   = blockIdx.y;
    const int q0   = (gridDim.x - 1 - blockIdx.x) * 128;   // heavy tiles first
    const int wr   = wid * 16;

    const int a_row = ((lane >> 3) & 1) * 8 + (lane & 7);
    const int a_kof = (lane >> 4) * 8;              // halves
    const int b_row = ((lane >> 4) & 1) * 8 + (lane & 7);
    const int b_q   = (lane >> 3) & 1;
    const int b_swb = b_row & 7;

    const __half* Qp = g_q + (long)bn * SS * DD;
    const __half* Kp = g_k + (long)bn * SS * DD;
    const __half* Vp = g_v + (long)bn * DD * SS;

    const int l_row0 = t >> 3;
    const int l_u    = t & 7;

    uint32_t Qf[4][4];
    {
        const __half* qr0 = Qp + (long)(q0 + wr + g) * DD;
        const __half* qr1 = qr0 + 8 * DD;
#pragma unroll
        for (int ks = 0; ks < 4; ks++) {
            Qf[ks][0] = *(const uint32_t*)(qr0 + ks * 16 + 2 * c);
            Qf[ks][1] = *(const uint32_t*)(qr1 + ks * 16 + 2 * c);
            Qf[ks][2] = *(const uint32_t*)(qr0 + ks * 16 + 2 * c + 8);
            Qf[ks][3] = *(const uint32_t*)(qr1 + ks * 16 + 2 * c + 8);
        }
    }

    float O[8][4];
#pragma unroll
    for (int dn = 0; dn < 8; dn++)
#pragma unroll
        for (int k = 0; k < 4; k++) O[dn][k] = 0.f;
    float m0v = -1e30f, m1v = -1e30f, l0 = 0.f, l1 = 0.f;

    const int r0g = q0 + wr + g;
    const int r1g = r0g + 8;
    const int nkt = (q0 + 128) >> 6;

    // prologue: tile 0 -> stage 0
#pragma unroll
    for (int p = 0; p < 2; p++) {
        const int row = l_row0 + p * 32;
        const int sc  = ((l_u ^ (row & 7)) * 8);
        cp_async16(smh + row * 64 + sc,        Kp + (long)row * DD + l_u * 8);
        cp_async16(smh + 8192 + row * 64 + sc, Vp + (long)row * SS + l_u * 8);
    }
    CP_COMMIT();

    for (int kt = 0; kt < nkt; kt++) {
        const int k0 = kt * 64;
        const int st = kt & 1;

        if (kt + 1 < nkt) {
            const int kn = k0 + 64;
            const int sn = st ^ 1;
#pragma unroll
            for (int p = 0; p < 2; p++) {
                const int row = l_row0 + p * 32;
                const int sc  = ((l_u ^ (row & 7)) * 8);
                cp_async16(smh + sn * AT_STG_H + row * 64 + sc,
                           Kp + (long)(kn + row) * DD + l_u * 8);
                cp_async16(smh + 8192 + sn * AT_STG_H + row * 64 + sc,
                           Vp + (long)row * SS + kn + l_u * 8);
            }
            CP_COMMIT();
            CP_WAIT(1);
        } else {
            CP_WAIT(0);
        }
        __syncthreads();

        const __half* Ks = smh + st * AT_STG_H;
        const __half* Vs = smh + 8192 + st * AT_STG_H;

        // ---- S = Q K^T ----
        float S[8][4];
#pragma unroll
        for (int ni = 0; ni < 8; ni++)
#pragma unroll
            for (int k = 0; k < 4; k++) S[ni][k] = 0.f;
#pragma unroll
        for (int ks = 0; ks < 4; ks++) {
            const int u = ((2 * ks + b_q) ^ b_swb) * 8;
#pragma unroll
            for (int nb = 0; nb < 4; nb++) {
                uint32_t bt[4];
                ldsm4(bt, Ks + (nb * 16 + b_row) * 64 + u);
                mma_f16(S[nb * 2 + 0], Qf[ks], &bt[0]);
                mma_f16(S[nb * 2 + 1], Qf[ks], &bt[2]);
            }
        }

        // causal mask: only diagonal-crossing tiles (warp-uniform fast path)
        if (k0 + 63 > q0 + wr) {
#pragma unroll
            for (int ni = 0; ni < 8; ni++) {
                const int col0 = k0 + ni * 8 + 2 * c;
                const int col1 = col0 + 1;
                if (col0 > r0g) S[ni][0] = -1e30f;
                if (col1 > r0g) S[ni][1] = -1e30f;
                if (col0 > r1g) S[ni][2] = -1e30f;
                if (col1 > r1g) S[ni][3] = -1e30f;
            }
        }

        // row max
        float mx0 = m0v, mx1 = m1v;
#pragma unroll
        for (int ni = 0; ni < 8; ni++) {
            mx0 = fmaxf(mx0, fmaxf(S[ni][0], S[ni][1]));
            mx1 = fmaxf(mx1, fmaxf(S[ni][2], S[ni][3]));
        }
        mx0 = fmaxf(mx0, __shfl_xor_sync(0xffffffffu, mx0, 1));
        mx0 = fmaxf(mx0, __shfl_xor_sync(0xffffffffu, mx0, 2));
        mx1 = fmaxf(mx1, __shfl_xor_sync(0xffffffffu, mx1, 1));
        mx1 = fmaxf(mx1, __shfl_xor_sync(0xffffffffu, mx1, 2));

        // exp2 domain: scores already carry log2e
        const float a0 = exp2f(m0v - mx0);
        const float a1 = exp2f(m1v - mx1);
        m0v = mx0; m1v = mx1;

        float rs0 = 0.f, rs1 = 0.f;
#pragma unroll
        for (int ni = 0; ni < 8; ni++) {
            float p00 = exp2f(S[ni][0] - mx0);
            float p01 = exp2f(S[ni][1] - mx0);
            float p10 = exp2f(S[ni][2] - mx1);
            float p11 = exp2f(S[ni][3] - mx1);
            rs0 += p00 + p01; rs1 += p10 + p11;
            *(uint32_t*)(Psb + (wr + g) * 72 + ni * 8 + 2 * c)     = pack_h2(p00, p01);
            *(uint32_t*)(Psb + (wr + g + 8) * 72 + ni * 8 + 2 * c) = pack_h2(p10, p11);
        }
        rs0 += __shfl_xor_sync(0xffffffffu, rs0, 1);
        rs0 += __shfl_xor_sync(0xffffffffu, rs0, 2);
        rs1 += __shfl_xor_sync(0xffffffffu, rs1, 1);
        rs1 += __shfl_xor_sync(0xffffffffu, rs1, 2);
        l0 = l0 * a0 + rs0;
        l1 = l1 * a1 + rs1;

#pragma unroll
        for (int dn = 0; dn < 8; dn++) {
            O[dn][0] *= a0; O[dn][1] *= a0;
            O[dn][2] *= a1; O[dn][3] *= a1;
        }
        __syncwarp();

        // ---- O += P @ V ----
#pragma unroll
        for (int j = 0; j < 4; j++) {
            uint32_t Af[4];
            ldsm4(Af, Psb + (wr + a_row) * 72 + j * 16 + a_kof);
            const int u = ((2 * j + b_q) ^ b_swb) * 8;
#pragma unroll
            for (int dnp = 0; dnp < 4; dnp++) {
                uint32_t bt[4];
                ldsm4(bt, Vs + (dnp * 16 + b_row) * 64 + u);
                mma_f16(O[dnp * 2 + 0], Af, &bt[0]);
                mma_f16(O[dnp * 2 + 1], Af, &bt[2]);
            }
        }
        __syncthreads();
    }

    // epilogue: O /= l, write g_o (fp16)
    const float inv0 = 1.0f / l0;
    const float inv1 = 1.0f / l1;
    const int b  = bn >> 4;
    const int hn = bn & 15;
    __half* orow0 = g_o + (long)(b * SS + r0g) * HH + hn * DD;
    __half* orow1 = orow0 + 8 * HH;
#pragma unroll
    for (int dn = 0; dn < 8; dn++) {
        *(uint32_t*)(orow0 + dn * 8 + 2 * c) = pack_h2(O[dn][0] * inv0, O[dn][1] * inv0);
        *(uint32_t*)(orow1 + dn * 8 + 2 * c) = pack_h2(O[dn][2] * inv1, O[dn][3] * inv1);
    }
}

// ---------------------------------------------------------------------------
extern "C" void kernel_launch(void* const* d_in, const int* in_sizes, int n_in,
                              void* d_out, int out_size)
{
    const float* hs    = (const float*)d_in[0];  // [B,S,H]
    const float* w_in  = (const float*)d_in[1];  // [3H,H]
    const float* b_in  = (const float*)d_in[2];  // [3H]
    const float* w_out = (const float*)d_in[3];  // [H,H]
    const float* b_out = (const float*)d_in[4];  // [H]
    float* out = (float*)d_out;                  // [B,S,H]

    (void)in_sizes; (void)n_in; (void)out_size;

    cudaFuncSetAttribute(gemm_mma<0>, cudaFuncAttributeMaxDynamicSharedMemorySize, SMEM_DYN);
    cudaFuncSetAttribute(gemm_mma<1>, cudaFuncAttributeMaxDynamicSharedMemorySize, SMEM_DYN);
    cudaFuncSetAttribute(flash_attn_mma, cudaFuncAttributeMaxDynamicSharedMemorySize, AT_SMEM);

    round_all<<<(NX4 + NWI4 + NWO4) / 256, 256>>>(
        (const float4*)hs, (const float4*)w_in, (const float4*)w_out);

    gemm_mma<0><<<dim3(K3H / NT, MM / MT), 256, SMEM_DYN>>>(b_in, nullptr);
    flash_attn_mma<<<dim3(SS / 128, BB * NH), 256, AT_SMEM>>>();
    gemm_mma<1><<<dim3(HH / NT, MM / MT), 256, SMEM_DYN>>>(b_out, out);
}